// round 7
// baseline (speedup 1.0000x reference)
#include <cuda_runtime.h>
#include <cuda_bf16.h>
#include <math.h>
#include <stdint.h>

#define SEQ 2048
#define DIM 4096
#define NH  32
#define HD  128
#define GK  12288   // 3-segment hi/lo K-concat: A=[hi|lo|hi], B=[hi|hi|lo]

// ---------------- scratch (__device__ globals; no cudaMalloc allowed) -------
__device__ __nv_bfloat16 g_wsplit[4ull * DIM * GK];      // weights  [hi|hi|lo]
__device__ __nv_bfloat16 g_xsplit[(size_t)SEQ * GK];     // x        [hi|lo|hi]
__device__ __nv_bfloat16 g_asplit[(size_t)SEQ * GK];     // attn out [hi|lo|hi]
__device__ __nv_bfloat16 g_qs[(size_t)SEQ * NH * 256];   // q per head [hi128|lo128]
__device__ __nv_bfloat16 g_ks[(size_t)SEQ * NH * 256];
__device__ __nv_bfloat16 g_vs[(size_t)SEQ * NH * 256];

// ---------------- PTX helpers ----------------------------------------------
__device__ __forceinline__ uint32_t smem_u32(const void* p) {
    uint32_t a;
    asm("{ .reg .u64 t; cvta.to.shared.u64 t, %1; cvt.u32.u64 %0, t; }" : "=r"(a) : "l"(p));
    return a;
}
__device__ __forceinline__ void cp_async16(uint32_t dst, const void* src) {
    asm volatile("cp.async.cg.shared.global [%0], [%1], 16;" :: "r"(dst), "l"(src));
}
#define CP_COMMIT()  asm volatile("cp.async.commit_group;" ::: "memory")
#define CP_WAIT(n)   asm volatile("cp.async.wait_group %0;" :: "n"(n) : "memory")

__device__ __forceinline__ void ldm_x4(uint32_t* r, uint32_t addr) {
    asm volatile("ldmatrix.sync.aligned.m8n8.x4.shared.b16 {%0,%1,%2,%3}, [%4];"
        : "=r"(r[0]), "=r"(r[1]), "=r"(r[2]), "=r"(r[3]) : "r"(addr));
}
__device__ __forceinline__ void ldm_x4_t(uint32_t* r, uint32_t addr) {
    asm volatile("ldmatrix.sync.aligned.m8n8.x4.trans.shared.b16 {%0,%1,%2,%3}, [%4];"
        : "=r"(r[0]), "=r"(r[1]), "=r"(r[2]), "=r"(r[3]) : "r"(addr));
}
__device__ __forceinline__ void mma16816(float* c, const uint32_t* a, uint32_t b0, uint32_t b1) {
    asm volatile(
        "mma.sync.aligned.m16n8k16.row.col.f32.bf16.bf16.f32 "
        "{%0,%1,%2,%3}, {%4,%5,%6,%7}, {%8,%9}, {%0,%1,%2,%3};"
        : "+f"(c[0]), "+f"(c[1]), "+f"(c[2]), "+f"(c[3])
        : "r"(a[0]), "r"(a[1]), "r"(a[2]), "r"(a[3]), "r"(b0), "r"(b1));
}
// pack two f32 -> bf16x2 (first arg in low half)
__device__ __forceinline__ uint32_t packbf2(float lo, float hi) {
    uint32_t r;
    asm("cvt.rn.bf16x2.f32 %0, %1, %2;" : "=r"(r) : "f"(hi), "f"(lo));
    return r;
}
__device__ __forceinline__ float bf_low(uint32_t r)  { return __uint_as_float(r << 16); }
__device__ __forceinline__ float bf_high(uint32_t r) { return __uint_as_float(r & 0xffff0000u); }

// ---------------- fp32 -> bf16 hi/lo split converters ----------------------
__device__ __forceinline__ void split4(const float4 v, __nv_bfloat16* hi, __nv_bfloat16* lo) {
    float f[4] = {v.x, v.y, v.z, v.w};
#pragma unroll
    for (int i = 0; i < 4; i++) {
        hi[i] = __float2bfloat16(f[i]);
        lo[i] = __float2bfloat16(f[i] - __bfloat162float(hi[i]));
    }
}

// Weights: [hi | hi | lo]
__global__ __launch_bounds__(256) void convert_w_kernel(
    const float* __restrict__ w0, const float* __restrict__ w1,
    const float* __restrict__ w2, const float* __restrict__ w3)
{
    const float* w = (blockIdx.z == 0) ? w0 : (blockIdx.z == 1) ? w1 :
                     (blockIdx.z == 2) ? w2 : w3;
    __nv_bfloat16* dst = g_wsplit + (size_t)blockIdx.z * DIM * GK;
    int idx = blockIdx.x * 256 + threadIdx.x;
    int row = idx >> 10;
    int c4  = (idx & 1023) << 2;
    __nv_bfloat16 hi[4], lo[4];
    split4(reinterpret_cast<const float4*>(w)[idx], hi, lo);
    size_t base = (size_t)row * GK + c4;
    *reinterpret_cast<uint2*>(dst + base)           = *reinterpret_cast<uint2*>(hi);
    *reinterpret_cast<uint2*>(dst + base + DIM)     = *reinterpret_cast<uint2*>(hi);
    *reinterpret_cast<uint2*>(dst + base + 2 * DIM) = *reinterpret_cast<uint2*>(lo);
}

// x: [hi | lo | hi]
__global__ __launch_bounds__(256) void convert_x_kernel(const float* __restrict__ x)
{
    int idx = blockIdx.x * 256 + threadIdx.x;
    int row = idx >> 10;
    int c4  = (idx & 1023) << 2;
    __nv_bfloat16 hi[4], lo[4];
    split4(reinterpret_cast<const float4*>(x)[idx], hi, lo);
    size_t base = (size_t)row * GK + c4;
    *reinterpret_cast<uint2*>(g_xsplit + base)           = *reinterpret_cast<uint2*>(hi);
    *reinterpret_cast<uint2*>(g_xsplit + base + DIM)     = *reinterpret_cast<uint2*>(lo);
    *reinterpret_cast<uint2*>(g_xsplit + base + 2 * DIM) = *reinterpret_cast<uint2*>(hi);
}

// ---------------- HMMA (mma.sync) bf16 GEMM ---------------------------------
// CTA tile 128x256, 8 warps (2m x 4n), warp tile 64x64, BK=32 double-buffered.
#define BK 32
#define NKSTEP (GK / BK)     // 384
#define ASTR 40              // bf16 elems per smem row (80B, conflict-free LDSM)
#define GEMM_SMEM ((2 * 128 * ASTR + 2 * 256 * ASTR) * (int)sizeof(__nv_bfloat16))

__device__ __forceinline__ void hgemm_body(
    const __nv_bfloat16* __restrict__ A,
    const __nv_bfloat16* __restrict__ B,
    float* __restrict__ C,                 // fp32 output (out-proj), or null
    __nv_bfloat16* __restrict__ qdst,      // per-head [hi|lo] output (qkv), or null
    const float* __restrict__ freqs, int rope, float qsc,
    int m0, int n0)
{
    extern __shared__ __nv_bfloat16 gsm[];
    __nv_bfloat16* sA = gsm;                 // 2 stages x 128 x ASTR
    __nv_bfloat16* sB = gsm + 2 * 128 * ASTR;// 2 stages x 256 x ASTR

    const int tid  = threadIdx.x;
    const int wid  = tid >> 5;
    const int lane = tid & 31;
    const int wm   = wid >> 2;   // 0..1 -> rows wm*64
    const int wn   = wid & 3;    // 0..3 -> cols wn*64

    float acc[4][8][4];
#pragma unroll
    for (int mi = 0; mi < 4; mi++)
#pragma unroll
        for (int ni = 0; ni < 8; ni++)
#pragma unroll
            for (int j = 0; j < 4; j++) acc[mi][ni][j] = 0.0f;

    const __nv_bfloat16* agp = A + (size_t)m0 * GK;
    const __nv_bfloat16* bgp = B + (size_t)n0 * GK;

    auto load_tile = [&](int kstep, int s) {
        const size_t koff = (size_t)kstep * BK;
        // A: 512 16B chunks (128 rows x 4)
        {
            int i = tid, r = i >> 2, seg = i & 3;
            cp_async16(smem_u32(sA + (s * 128 + r) * ASTR + seg * 8),
                       agp + (size_t)r * GK + koff + seg * 8);
            i = tid + 256; r = i >> 2; seg = i & 3;
            cp_async16(smem_u32(sA + (s * 128 + r) * ASTR + seg * 8),
                       agp + (size_t)r * GK + koff + seg * 8);
        }
        // B: 1024 16B chunks (256 rows x 4)
#pragma unroll
        for (int l = 0; l < 4; l++) {
            int i = tid + l * 256, r = i >> 2, seg = i & 3;
            cp_async16(smem_u32(sB + (s * 256 + r) * ASTR + seg * 8),
                       bgp + (size_t)r * GK + koff + seg * 8);
        }
        CP_COMMIT();
    };

    load_tile(0, 0);

    for (int k = 0; k < NKSTEP; k++) {
        if (k + 1 < NKSTEP) {
            load_tile(k + 1, (k + 1) & 1);
            CP_WAIT(1);
        } else {
            CP_WAIT(0);
        }
        __syncthreads();
        const int s = k & 1;

#pragma unroll
        for (int kk = 0; kk < 2; kk++) {
            const int k0 = kk * 16;
            uint32_t af[4][4], bf[8][2];
#pragma unroll
            for (int mi = 0; mi < 4; mi++) {
                int row = wm * 64 + mi * 16 + (lane & 15);
                ldm_x4(af[mi], smem_u32(sA + (s * 128 + row) * ASTR + k0 + ((lane >> 4) << 3)));
            }
#pragma unroll
            for (int np = 0; np < 4; np++) {
                int rown = wn * 64 + np * 16 + ((lane >> 4) << 3) + (lane & 7);
                uint32_t b[4];
                ldm_x4(b, smem_u32(sB + (s * 256 + rown) * ASTR + k0 + (((lane >> 3) & 1) << 3)));
                bf[2 * np][0] = b[0];  bf[2 * np][1] = b[1];
                bf[2 * np + 1][0] = b[2];  bf[2 * np + 1][1] = b[3];
            }
#pragma unroll
            for (int mi = 0; mi < 4; mi++)
#pragma unroll
                for (int ni = 0; ni < 8; ni++)
                    mma16816(acc[mi][ni], af[mi], bf[ni][0], bf[ni][1]);
        }
        __syncthreads();
    }

#pragma unroll
    for (int mi = 0; mi < 4; mi++) {
        const int ra = m0 + wm * 64 + mi * 16 + (lane >> 2);
        const int rb = ra + 8;
#pragma unroll
        for (int ni = 0; ni < 8; ni++) {
            const int col = n0 + wn * 64 + ni * 8 + ((lane & 3) << 1);
            float d0 = acc[mi][ni][0], d1 = acc[mi][ni][1];
            float d2 = acc[mi][ni][2], d3 = acc[mi][ni][3];
            if (rope) {
                const int hd = col & (HD - 1);          // even
                float ca = freqs[ra * HD + hd], sa = freqs[ra * HD + hd + 1];
                float cb = freqs[rb * HD + hd], sb = freqs[rb * HD + hd + 1];
                d0 *= (ca - sa) * qsc;  d1 *= (ca + sa) * qsc;
                d2 *= (cb - sb) * qsc;  d3 *= (cb + sb) * qsc;
            }
            if (qdst) {
                const int head = col >> 7, d = col & 127;
                __nv_bfloat16* pa = qdst + ((size_t)ra * NH + head) * 256 + d;
                uint32_t hi = packbf2(d0, d1);
                uint32_t lo = packbf2(d0 - bf_low(hi), d1 - bf_high(hi));
                *reinterpret_cast<uint32_t*>(pa)       = hi;
                *reinterpret_cast<uint32_t*>(pa + 128) = lo;
                __nv_bfloat16* pb = qdst + ((size_t)rb * NH + head) * 256 + d;
                hi = packbf2(d2, d3);
                lo = packbf2(d2 - bf_low(hi), d3 - bf_high(hi));
                *reinterpret_cast<uint32_t*>(pb)       = hi;
                *reinterpret_cast<uint32_t*>(pb + 128) = lo;
            } else {
                *reinterpret_cast<float2*>(&C[(size_t)ra * DIM + col]) = make_float2(d0, d1);
                *reinterpret_cast<float2*>(&C[(size_t)rb * DIM + col]) = make_float2(d2, d3);
            }
        }
    }
}

__global__ __launch_bounds__(256, 1) void qkv_gemm_kernel(const float* __restrict__ freqs)
{
    const int z = blockIdx.z;
    const __nv_bfloat16* B = g_wsplit + (size_t)z * DIM * GK;
    __nv_bfloat16* dst = (z == 0) ? g_qs : (z == 1) ? g_ks : g_vs;
    const float qsc = (z == 0) ? 0.08838834764831845f : 1.0f;
    hgemm_body(g_xsplit, B, nullptr, dst, freqs, (z < 2) ? 1 : 0, qsc,
               blockIdx.x * 128, blockIdx.y * 256);
}

__global__ __launch_bounds__(256, 1) void out_gemm_kernel(float* __restrict__ out)
{
    hgemm_body(g_asplit, g_wsplit + 3ull * DIM * GK, out, nullptr, nullptr, 0, 1.0f,
               blockIdx.x * 128, blockIdx.y * 256);
}

// ---------------- HMMA flash attention (unchanged from R6) ------------------
#define AQS 264
#define ATTN_SMEM ((128 + 128 + 128) * AQS * 2)

__global__ __launch_bounds__(256, 1) void attn_kernel()
{
    extern __shared__ __nv_bfloat16 sm_attn[];
    __nv_bfloat16* sQ = sm_attn;
    __nv_bfloat16* sK = sQ + 128 * AQS;
    __nv_bfloat16* sV = sK + 2 * 64 * AQS;

    const int h   = blockIdx.y;
    const int q0  = blockIdx.x * 128;
    const int tid = threadIdx.x;
    const int wid = tid >> 5, lane = tid & 31;

    for (int i = tid; i < 128 * 32; i += 256) {
        int r = i >> 5, c = i & 31;
        cp_async16(smem_u32(sQ + r * AQS) + c * 16,
                   g_qs + ((size_t)(q0 + r) * NH + h) * 256 + c * 8);
    }
    CP_COMMIT();

    const int nt = q0 / 64 + 2;

    auto load_kv = [&](int t, int s) {
        for (int i = tid; i < 64 * 32; i += 256) {
            int r = i >> 5, c = i & 31;
            size_t src = ((size_t)(t * 64 + r) * NH + h) * 256 + c * 8;
            cp_async16(smem_u32(sK + (s * 64 + r) * AQS) + c * 16, g_ks + src);
            cp_async16(smem_u32(sV + (s * 64 + r) * AQS) + c * 16, g_vs + src);
        }
        CP_COMMIT();
    };
    load_kv(0, 0);

    float m0 = -1e30f, m1 = -1e30f, l0 = 0.0f, l1 = 0.0f;
    float O[16][4];
#pragma unroll
    for (int n = 0; n < 16; n++)
#pragma unroll
        for (int j = 0; j < 4; j++) O[n][j] = 0.0f;

    const int wrow = q0 + wid * 16;
    const int r0g  = wrow + (lane >> 2);
    const uint32_t Qb = smem_u32(sQ);
    const uint32_t qrow_off = (uint32_t)((wid * 16 + (lane & 15)) * AQS + ((lane >> 4) << 3));
    const uint32_t krow = (uint32_t)(((lane >> 4) << 3) + (lane & 7));
    const uint32_t kcol = (uint32_t)(((lane >> 3) & 1) << 3);
    const uint32_t vrow_off = (uint32_t)(lane & 15);
    const uint32_t vcol8 = (uint32_t)((lane >> 4) << 3);

    for (int t = 0; t < nt; t++) {
        if (t + 1 < nt) { load_kv(t + 1, (t + 1) & 1); CP_WAIT(1); }
        else           { CP_WAIT(0); }
        __syncthreads();
        const int k0 = t * 64;

        if (k0 <= wrow + 15) {
            const uint32_t Kb = smem_u32(sK + (t & 1) * 64 * AQS);
            const uint32_t Vb = smem_u32(sV + (t & 1) * 64 * AQS);

            float s[8][4];
#pragma unroll
            for (int j = 0; j < 8; j++)
#pragma unroll
                for (int i = 0; i < 4; i++) s[j][i] = 0.0f;

#pragma unroll
            for (int kk = 0; kk < 8; kk++) {
                uint32_t qh[4], ql[4];
                ldm_x4(qh, Qb + (qrow_off + kk * 16) * 2);
                ldm_x4(ql, Qb + (qrow_off + 128 + kk * 16) * 2);
#pragma unroll
                for (int g = 0; g < 4; g++) {
                    uint32_t kb[4];
                    uint32_t base = Kb + ((g * 16 + krow) * AQS + kcol + kk * 16) * 2;
                    ldm_x4(kb, base);
                    mma16816(s[2 * g],     qh, kb[0], kb[1]);
                    mma16816(s[2 * g + 1], qh, kb[2], kb[3]);
                    mma16816(s[2 * g],     ql, kb[0], kb[1]);
                    mma16816(s[2 * g + 1], ql, kb[2], kb[3]);
                    ldm_x4(kb, base + 256);
                    mma16816(s[2 * g],     qh, kb[0], kb[1]);
                    mma16816(s[2 * g + 1], qh, kb[2], kb[3]);
                }
            }

            if (k0 + 63 > wrow) {
                const int c0 = k0 + ((lane & 3) << 1);
#pragma unroll
                for (int j = 0; j < 8; j++) {
                    int cc = c0 + j * 8;
                    if (cc     > r0g)     s[j][0] = -1e30f;
                    if (cc + 1 > r0g)     s[j][1] = -1e30f;
                    if (cc     > r0g + 8) s[j][2] = -1e30f;
                    if (cc + 1 > r0g + 8) s[j][3] = -1e30f;
                }
            }

            float mt0 = -1e30f, mt1 = -1e30f;
#pragma unroll
            for (int j = 0; j < 8; j++) {
                mt0 = fmaxf(mt0, fmaxf(s[j][0], s[j][1]));
                mt1 = fmaxf(mt1, fmaxf(s[j][2], s[j][3]));
            }
            mt0 = fmaxf(mt0, __shfl_xor_sync(0xffffffffu, mt0, 1));
            mt0 = fmaxf(mt0, __shfl_xor_sync(0xffffffffu, mt0, 2));
            mt1 = fmaxf(mt1, __shfl_xor_sync(0xffffffffu, mt1, 1));
            mt1 = fmaxf(mt1, __shfl_xor_sync(0xffffffffu, mt1, 2));
            const float mn0 = fmaxf(m0, mt0), mn1 = fmaxf(m1, mt1);
            const float corr0 = __expf(m0 - mn0), corr1 = __expf(m1 - mn1);
            m0 = mn0; m1 = mn1;
            float rs0 = 0.0f, rs1 = 0.0f;
#pragma unroll
            for (int j = 0; j < 8; j++) {
                s[j][0] = __expf(s[j][0] - mn0);
                s[j][1] = __expf(s[j][1] - mn0);
                s[j][2] = __expf(s[j][2] - mn1);
                s[j][3] = __expf(s[j][3] - mn1);
                rs0 += s[j][0] + s[j][1];
                rs1 += s[j][2] + s[j][3];
            }
            rs0 += __shfl_xor_sync(0xffffffffu, rs0, 1);
            rs0 += __shfl_xor_sync(0xffffffffu, rs0, 2);
            rs1 += __shfl_xor_sync(0xffffffffu, rs1, 1);
            rs1 += __shfl_xor_sync(0xffffffffu, rs1, 2);
            l0 = l0 * corr0 + rs0;
            l1 = l1 * corr1 + rs1;
#pragma unroll
            for (int n = 0; n < 16; n++) {
                O[n][0] *= corr0;  O[n][1] *= corr0;
                O[n][2] *= corr1;  O[n][3] *= corr1;
            }

#pragma unroll
            for (int kt = 0; kt < 4; kt++) {
                uint32_t ph[4], pl[4];
                ph[0] = packbf2(s[2 * kt][0], s[2 * kt][1]);
                pl[0] = packbf2(s[2 * kt][0] - bf_low(ph[0]), s[2 * kt][1] - bf_high(ph[0]));
                ph[1] = packbf2(s[2 * kt][2], s[2 * kt][3]);
                pl[1] = packbf2(s[2 * kt][2] - bf_low(ph[1]), s[2 * kt][3] - bf_high(ph[1]));
                ph[2] = packbf2(s[2 * kt + 1][0], s[2 * kt + 1][1]);
                pl[2] = packbf2(s[2 * kt + 1][0] - bf_low(ph[2]), s[2 * kt + 1][1] - bf_high(ph[2]));
                ph[3] = packbf2(s[2 * kt + 1][2], s[2 * kt + 1][3]);
                pl[3] = packbf2(s[2 * kt + 1][2] - bf_low(ph[3]), s[2 * kt + 1][3] - bf_high(ph[3]));
#pragma unroll
                for (int g = 0; g < 8; g++) {
                    uint32_t vb[4];
                    uint32_t base = Vb + ((kt * 16 + vrow_off) * AQS + g * 16 + vcol8) * 2;
                    ldm_x4_t(vb, base);
                    mma16816(O[2 * g],     ph, vb[0], vb[1]);
                    mma16816(O[2 * g + 1], ph, vb[2], vb[3]);
                    mma16816(O[2 * g],     pl, vb[0], vb[1]);
                    mma16816(O[2 * g + 1], pl, vb[2], vb[3]);
                    ldm_x4_t(vb, base + 256);
                    mma16816(O[2 * g],     ph, vb[0], vb[1]);
                    mma16816(O[2 * g + 1], ph, vb[2], vb[3]);
                }
            }
        }
        __syncthreads();
    }

    const float inv0 = 1.0f / l0, inv1 = 1.0f / l1;
    const int sr0 = wrow + (lane >> 2), sr1 = sr0 + 8;
#pragma unroll
    for (int n = 0; n < 16; n++) {
        const int d = n * 8 + ((lane & 3) << 1);
        {
            float v0 = O[n][0] * inv0, v1 = O[n][1] * inv0;
            uint32_t hi = packbf2(v0, v1);
            uint32_t lo = packbf2(v0 - bf_low(hi), v1 - bf_high(hi));
            __nv_bfloat16* p = g_asplit + (size_t)sr0 * GK + h * 128 + d;
            *reinterpret_cast<uint32_t*>(p)            = hi;
            *reinterpret_cast<uint32_t*>(p + DIM)      = lo;
            *reinterpret_cast<uint32_t*>(p + 2 * DIM)  = hi;
        }
        {
            float v2 = O[n][2] * inv1, v3 = O[n][3] * inv1;
            uint32_t hi = packbf2(v2, v3);
            uint32_t lo = packbf2(v2 - bf_low(hi), v3 - bf_high(hi));
            __nv_bfloat16* p = g_asplit + (size_t)sr1 * GK + h * 128 + d;
            *reinterpret_cast<uint32_t*>(p)            = hi;
            *reinterpret_cast<uint32_t*>(p + DIM)      = lo;
            *reinterpret_cast<uint32_t*>(p + 2 * DIM)  = hi;
        }
    }
}

// ---------------- launch -----------------------------------------------------
// inputs: 0:x 1:start_pos 2:freqs 3:mask 4:wq 5:wk 6:wv 7:wo  (mask analytic)
extern "C" void kernel_launch(void* const* d_in, const int* in_sizes, int n_in,
                              void* d_out, int out_size)
{
    const float* x     = (const float*)d_in[0];
    const float* freqs = (const float*)d_in[2];
    const float* wq    = (const float*)d_in[4];
    const float* wk    = (const float*)d_in[5];
    const float* wv    = (const float*)d_in[6];
    const float* wo    = (const float*)d_in[7];
    float* out = (float*)d_out;

    cudaFuncSetAttribute(attn_kernel,     cudaFuncAttributeMaxDynamicSharedMemorySize, ATTN_SMEM);
    cudaFuncSetAttribute(qkv_gemm_kernel, cudaFuncAttributeMaxDynamicSharedMemorySize, GEMM_SMEM);
    cudaFuncSetAttribute(out_gemm_kernel, cudaFuncAttributeMaxDynamicSharedMemorySize, GEMM_SMEM);

    convert_w_kernel<<<dim3(DIM * DIM / 4 / 256, 1, 4), 256>>>(wq, wk, wv, wo);
    convert_x_kernel<<<SEQ * DIM / 4 / 256, 256>>>(x);
    qkv_gemm_kernel<<<dim3(SEQ / 128, DIM / 256, 3), 256, GEMM_SMEM>>>(freqs);
    attn_kernel<<<dim3(SEQ / 128, NH), 256, ATTN_SMEM>>>();
    out_gemm_kernel<<<dim3(SEQ / 128, DIM / 256, 1), 256, GEMM_SMEM>>>(out);
}

// round 8
// speedup vs baseline: 2.5305x; 2.5305x over previous
#include <cuda_runtime.h>
#include <cuda_bf16.h>
#include <cuda_fp16.h>
#include <math.h>
#include <stdint.h>

#define SEQ 2048
#define DIM 4096
#define NH  32
#define HD  128
#define GK  8192    // 2-segment fp16 K-concat: A=[hi|lo], B=[hi|hi]

// ---------------- scratch (__device__ globals; no cudaMalloc allowed) -------
__device__ __half g_wsplit[4ull * DIM * GK];             // weights  [hi|hi] fp16
__device__ __half g_xsplit[(size_t)SEQ * GK];            // x        [hi|lo] fp16
__device__ __half g_asplit[(size_t)SEQ * GK];            // attn out [hi|lo] fp16
__device__ __nv_bfloat16 g_qs[(size_t)SEQ * NH * 256];   // q per head [hi128|lo128] bf16
__device__ __nv_bfloat16 g_ks[(size_t)SEQ * NH * 256];
__device__ __nv_bfloat16 g_vs[(size_t)SEQ * NH * 256];

// ---------------- PTX helpers ----------------------------------------------
__device__ __forceinline__ uint32_t smem_u32(const void* p) {
    uint32_t a;
    asm("{ .reg .u64 t; cvta.to.shared.u64 t, %1; cvt.u32.u64 %0, t; }" : "=r"(a) : "l"(p));
    return a;
}
__device__ __forceinline__ void cp_async16(uint32_t dst, const void* src) {
    asm volatile("cp.async.cg.shared.global [%0], [%1], 16;" :: "r"(dst), "l"(src));
}
#define CP_COMMIT()  asm volatile("cp.async.commit_group;" ::: "memory")
#define CP_WAIT(n)   asm volatile("cp.async.wait_group %0;" :: "n"(n) : "memory")

__device__ __forceinline__ void ldm_x4(uint32_t* r, uint32_t addr) {
    asm volatile("ldmatrix.sync.aligned.m8n8.x4.shared.b16 {%0,%1,%2,%3}, [%4];"
        : "=r"(r[0]), "=r"(r[1]), "=r"(r[2]), "=r"(r[3]) : "r"(addr));
}
__device__ __forceinline__ void ldm_x4_t(uint32_t* r, uint32_t addr) {
    asm volatile("ldmatrix.sync.aligned.m8n8.x4.trans.shared.b16 {%0,%1,%2,%3}, [%4];"
        : "=r"(r[0]), "=r"(r[1]), "=r"(r[2]), "=r"(r[3]) : "r"(addr));
}
// bf16 mma (attention)
__device__ __forceinline__ void mma16816(float* c, const uint32_t* a, uint32_t b0, uint32_t b1) {
    asm volatile(
        "mma.sync.aligned.m16n8k16.row.col.f32.bf16.bf16.f32 "
        "{%0,%1,%2,%3}, {%4,%5,%6,%7}, {%8,%9}, {%0,%1,%2,%3};"
        : "+f"(c[0]), "+f"(c[1]), "+f"(c[2]), "+f"(c[3])
        : "r"(a[0]), "r"(a[1]), "r"(a[2]), "r"(a[3]), "r"(b0), "r"(b1));
}
// fp16 mma (projection GEMMs), fp32 accum
__device__ __forceinline__ void mma16816h(float* c, const uint32_t* a, uint32_t b0, uint32_t b1) {
    asm volatile(
        "mma.sync.aligned.m16n8k16.row.col.f32.f16.f16.f32 "
        "{%0,%1,%2,%3}, {%4,%5,%6,%7}, {%8,%9}, {%0,%1,%2,%3};"
        : "+f"(c[0]), "+f"(c[1]), "+f"(c[2]), "+f"(c[3])
        : "r"(a[0]), "r"(a[1]), "r"(a[2]), "r"(a[3]), "r"(b0), "r"(b1));
}
// pack two f32 -> bf16x2 (first arg in low half)
__device__ __forceinline__ uint32_t packbf2(float lo, float hi) {
    uint32_t r;
    asm("cvt.rn.bf16x2.f32 %0, %1, %2;" : "=r"(r) : "f"(hi), "f"(lo));
    return r;
}
__device__ __forceinline__ float bf_low(uint32_t r)  { return __uint_as_float(r << 16); }
__device__ __forceinline__ float bf_high(uint32_t r) { return __uint_as_float(r & 0xffff0000u); }

// ---------------- fp32 -> fp16 hi/lo split converters -----------------------
__device__ __forceinline__ void split4h(const float4 v, __half* hi, __half* lo) {
    float f[4] = {v.x, v.y, v.z, v.w};
#pragma unroll
    for (int i = 0; i < 4; i++) {
        hi[i] = __float2half_rn(f[i]);
        lo[i] = __float2half_rn(f[i] - __half2float(hi[i]));
    }
}

// Weights: [hi | hi]
__global__ __launch_bounds__(256) void convert_w_kernel(
    const float* __restrict__ w0, const float* __restrict__ w1,
    const float* __restrict__ w2, const float* __restrict__ w3)
{
    const float* w = (blockIdx.z == 0) ? w0 : (blockIdx.z == 1) ? w1 :
                     (blockIdx.z == 2) ? w2 : w3;
    __half* dst = g_wsplit + (size_t)blockIdx.z * DIM * GK;
    int idx = blockIdx.x * 256 + threadIdx.x;
    int row = idx >> 10;
    int c4  = (idx & 1023) << 2;
    __half hi[4], lo[4];
    split4h(reinterpret_cast<const float4*>(w)[idx], hi, lo);
    size_t base = (size_t)row * GK + c4;
    *reinterpret_cast<uint2*>(dst + base)       = *reinterpret_cast<uint2*>(hi);
    *reinterpret_cast<uint2*>(dst + base + DIM) = *reinterpret_cast<uint2*>(hi);
}

// x: [hi | lo]
__global__ __launch_bounds__(256) void convert_x_kernel(const float* __restrict__ x)
{
    int idx = blockIdx.x * 256 + threadIdx.x;
    int row = idx >> 10;
    int c4  = (idx & 1023) << 2;
    __half hi[4], lo[4];
    split4h(reinterpret_cast<const float4*>(x)[idx], hi, lo);
    size_t base = (size_t)row * GK + c4;
    *reinterpret_cast<uint2*>(g_xsplit + base)       = *reinterpret_cast<uint2*>(hi);
    *reinterpret_cast<uint2*>(g_xsplit + base + DIM) = *reinterpret_cast<uint2*>(lo);
}

// ---------------- HMMA (mma.sync) fp16 GEMM — R6 geometry -------------------
// C[128x128] = A'[M,GK] . B'[N,GK]^T ; 256 threads, 8 warps (4m x 2n),
// warp tile 32x64, BK=32 double-buffered cp.async, pad-40 smem rows.
#define BK 32
#define NKSTEP (GK / BK)     // 256
#define ASTR 40

__device__ __forceinline__ void hgemm_body(
    const __half* __restrict__ A,
    const __half* __restrict__ B,
    float* __restrict__ C,                 // fp32 output (out-proj), or null
    __nv_bfloat16* __restrict__ qdst,      // per-head [hi|lo] output (qkv), or null
    const float* __restrict__ freqs, int rope, float qsc,
    int m0, int n0)
{
    __shared__ __half sA[2][128 * ASTR];
    __shared__ __half sB[2][128 * ASTR];

    const int tid  = threadIdx.x;
    const int wid  = tid >> 5;
    const int lane = tid & 31;
    const int wm   = wid >> 1;   // 0..3 -> rows wm*32
    const int wn   = wid & 1;    // 0..1 -> cols wn*64

    float acc[2][8][4];
#pragma unroll
    for (int mi = 0; mi < 2; mi++)
#pragma unroll
        for (int ni = 0; ni < 8; ni++)
#pragma unroll
            for (int j = 0; j < 4; j++) acc[mi][ni][j] = 0.0f;

    const __half* agp = A + (size_t)m0 * GK;
    const __half* bgp = B + (size_t)n0 * GK;

    const int r0c = tid >> 2, seg0 = (tid & 3);
    const int r1c = (tid + 256) >> 2, seg1 = ((tid + 256) & 3);

    auto load_tile = [&](int kstep, int s) {
        const size_t koff = (size_t)kstep * BK;
        cp_async16(smem_u32(&sA[s][r0c * ASTR + seg0 * 8]), agp + (size_t)r0c * GK + koff + seg0 * 8);
        cp_async16(smem_u32(&sB[s][r0c * ASTR + seg0 * 8]), bgp + (size_t)r0c * GK + koff + seg0 * 8);
        cp_async16(smem_u32(&sA[s][r1c * ASTR + seg1 * 8]), agp + (size_t)r1c * GK + koff + seg1 * 8);
        cp_async16(smem_u32(&sB[s][r1c * ASTR + seg1 * 8]), bgp + (size_t)r1c * GK + koff + seg1 * 8);
        CP_COMMIT();
    };

    load_tile(0, 0);

    for (int k = 0; k < NKSTEP; k++) {
        if (k + 1 < NKSTEP) {
            load_tile(k + 1, (k + 1) & 1);
            CP_WAIT(1);
        } else {
            CP_WAIT(0);
        }
        __syncthreads();
        const int s = k & 1;

#pragma unroll
        for (int kk = 0; kk < 2; kk++) {
            const int k0 = kk * 16;
            uint32_t af[2][4], bf[8][2];
#pragma unroll
            for (int mi = 0; mi < 2; mi++) {
                int row = wm * 32 + mi * 16 + (lane & 15);
                ldm_x4(af[mi], smem_u32(&sA[s][row * ASTR + k0 + ((lane >> 4) << 3)]));
            }
#pragma unroll
            for (int np = 0; np < 4; np++) {
                int rown = wn * 64 + np * 16 + ((lane >> 4) << 3) + (lane & 7);
                uint32_t b[4];
                ldm_x4(b, smem_u32(&sB[s][rown * ASTR + k0 + (((lane >> 3) & 1) << 3)]));
                bf[2 * np][0] = b[0];  bf[2 * np][1] = b[1];
                bf[2 * np + 1][0] = b[2];  bf[2 * np + 1][1] = b[3];
            }
#pragma unroll
            for (int mi = 0; mi < 2; mi++)
#pragma unroll
                for (int ni = 0; ni < 8; ni++)
                    mma16816h(acc[mi][ni], af[mi], bf[ni][0], bf[ni][1]);
        }
        __syncthreads();
    }

#pragma unroll
    for (int mi = 0; mi < 2; mi++) {
        const int ra = m0 + wm * 32 + mi * 16 + (lane >> 2);
        const int rb = ra + 8;
#pragma unroll
        for (int ni = 0; ni < 8; ni++) {
            const int col = n0 + wn * 64 + ni * 8 + ((lane & 3) << 1);
            float d0 = acc[mi][ni][0], d1 = acc[mi][ni][1];
            float d2 = acc[mi][ni][2], d3 = acc[mi][ni][3];
            if (rope) {
                const int hd = col & (HD - 1);          // even
                float ca = freqs[ra * HD + hd], sa = freqs[ra * HD + hd + 1];
                float cb = freqs[rb * HD + hd], sb = freqs[rb * HD + hd + 1];
                d0 *= (ca - sa) * qsc;  d1 *= (ca + sa) * qsc;
                d2 *= (cb - sb) * qsc;  d3 *= (cb + sb) * qsc;
            }
            if (qdst) {
                const int head = col >> 7, d = col & 127;
                __nv_bfloat16* pa = qdst + ((size_t)ra * NH + head) * 256 + d;
                uint32_t hi = packbf2(d0, d1);
                uint32_t lo = packbf2(d0 - bf_low(hi), d1 - bf_high(hi));
                *reinterpret_cast<uint32_t*>(pa)       = hi;
                *reinterpret_cast<uint32_t*>(pa + 128) = lo;
                __nv_bfloat16* pb = qdst + ((size_t)rb * NH + head) * 256 + d;
                hi = packbf2(d2, d3);
                lo = packbf2(d2 - bf_low(hi), d3 - bf_high(hi));
                *reinterpret_cast<uint32_t*>(pb)       = hi;
                *reinterpret_cast<uint32_t*>(pb + 128) = lo;
            } else {
                *reinterpret_cast<float2*>(&C[(size_t)ra * DIM + col]) = make_float2(d0, d1);
                *reinterpret_cast<float2*>(&C[(size_t)rb * DIM + col]) = make_float2(d2, d3);
            }
        }
    }
}

__global__ __launch_bounds__(256, 2) void qkv_gemm_kernel(const float* __restrict__ freqs)
{
    const int z = blockIdx.z;
    const __half* B = g_wsplit + (size_t)z * DIM * GK;
    __nv_bfloat16* dst = (z == 0) ? g_qs : (z == 1) ? g_ks : g_vs;
    const float qsc = (z == 0) ? 0.08838834764831845f : 1.0f;
    hgemm_body(g_xsplit, B, nullptr, dst, freqs, (z < 2) ? 1 : 0, qsc,
               blockIdx.x * 128, blockIdx.y * 128);
}

__global__ __launch_bounds__(256, 2) void out_gemm_kernel(float* __restrict__ out)
{
    hgemm_body(g_asplit, g_wsplit + 3ull * DIM * GK, out, nullptr, nullptr, 0, 1.0f,
               blockIdx.x * 128, blockIdx.y * 128);
}

// ---------------- HMMA flash attention (bf16 3-segment, as R6) --------------
#define AQS 264
#define ATTN_SMEM ((128 + 128 + 128) * AQS * 2)

__global__ __launch_bounds__(256, 1) void attn_kernel()
{
    extern __shared__ __nv_bfloat16 sm_attn[];
    __nv_bfloat16* sQ = sm_attn;
    __nv_bfloat16* sK = sQ + 128 * AQS;
    __nv_bfloat16* sV = sK + 2 * 64 * AQS;

    const int h   = blockIdx.y;
    const int q0  = blockIdx.x * 128;
    const int tid = threadIdx.x;
    const int wid = tid >> 5, lane = tid & 31;

    for (int i = tid; i < 128 * 32; i += 256) {
        int r = i >> 5, c = i & 31;
        cp_async16(smem_u32(sQ + r * AQS) + c * 16,
                   g_qs + ((size_t)(q0 + r) * NH + h) * 256 + c * 8);
    }
    CP_COMMIT();

    const int nt = q0 / 64 + 2;

    auto load_kv = [&](int t, int s) {
        for (int i = tid; i < 64 * 32; i += 256) {
            int r = i >> 5, c = i & 31;
            size_t src = ((size_t)(t * 64 + r) * NH + h) * 256 + c * 8;
            cp_async16(smem_u32(sK + (s * 64 + r) * AQS) + c * 16, g_ks + src);
            cp_async16(smem_u32(sV + (s * 64 + r) * AQS) + c * 16, g_vs + src);
        }
        CP_COMMIT();
    };
    load_kv(0, 0);

    float m0 = -1e30f, m1 = -1e30f, l0 = 0.0f, l1 = 0.0f;
    float O[16][4];
#pragma unroll
    for (int n = 0; n < 16; n++)
#pragma unroll
        for (int j = 0; j < 4; j++) O[n][j] = 0.0f;

    const int wrow = q0 + wid * 16;
    const int r0g  = wrow + (lane >> 2);
    const uint32_t Qb = smem_u32(sQ);
    const uint32_t qrow_off = (uint32_t)((wid * 16 + (lane & 15)) * AQS + ((lane >> 4) << 3));
    const uint32_t krow = (uint32_t)(((lane >> 4) << 3) + (lane & 7));
    const uint32_t kcol = (uint32_t)(((lane >> 3) & 1) << 3);
    const uint32_t vrow_off = (uint32_t)(lane & 15);
    const uint32_t vcol8 = (uint32_t)((lane >> 4) << 3);

    for (int t = 0; t < nt; t++) {
        if (t + 1 < nt) { load_kv(t + 1, (t + 1) & 1); CP_WAIT(1); }
        else           { CP_WAIT(0); }
        __syncthreads();
        const int k0 = t * 64;

        if (k0 <= wrow + 15) {
            const uint32_t Kb = smem_u32(sK + (t & 1) * 64 * AQS);
            const uint32_t Vb = smem_u32(sV + (t & 1) * 64 * AQS);

            float s[8][4];
#pragma unroll
            for (int j = 0; j < 8; j++)
#pragma unroll
                for (int i = 0; i < 4; i++) s[j][i] = 0.0f;

#pragma unroll
            for (int kk = 0; kk < 8; kk++) {
                uint32_t qh[4], ql[4];
                ldm_x4(qh, Qb + (qrow_off + kk * 16) * 2);
                ldm_x4(ql, Qb + (qrow_off + 128 + kk * 16) * 2);
#pragma unroll
                for (int g = 0; g < 4; g++) {
                    uint32_t kb[4];
                    uint32_t base = Kb + ((g * 16 + krow) * AQS + kcol + kk * 16) * 2;
                    ldm_x4(kb, base);
                    mma16816(s[2 * g],     qh, kb[0], kb[1]);
                    mma16816(s[2 * g + 1], qh, kb[2], kb[3]);
                    mma16816(s[2 * g],     ql, kb[0], kb[1]);
                    mma16816(s[2 * g + 1], ql, kb[2], kb[3]);
                    ldm_x4(kb, base + 256);
                    mma16816(s[2 * g],     qh, kb[0], kb[1]);
                    mma16816(s[2 * g + 1], qh, kb[2], kb[3]);
                }
            }

            if (k0 + 63 > wrow) {
                const int c0 = k0 + ((lane & 3) << 1);
#pragma unroll
                for (int j = 0; j < 8; j++) {
                    int cc = c0 + j * 8;
                    if (cc     > r0g)     s[j][0] = -1e30f;
                    if (cc + 1 > r0g)     s[j][1] = -1e30f;
                    if (cc     > r0g + 8) s[j][2] = -1e30f;
                    if (cc + 1 > r0g + 8) s[j][3] = -1e30f;
                }
            }

            float mt0 = -1e30f, mt1 = -1e30f;
#pragma unroll
            for (int j = 0; j < 8; j++) {
                mt0 = fmaxf(mt0, fmaxf(s[j][0], s[j][1]));
                mt1 = fmaxf(mt1, fmaxf(s[j][2], s[j][3]));
            }
            mt0 = fmaxf(mt0, __shfl_xor_sync(0xffffffffu, mt0, 1));
            mt0 = fmaxf(mt0, __shfl_xor_sync(0xffffffffu, mt0, 2));
            mt1 = fmaxf(mt1, __shfl_xor_sync(0xffffffffu, mt1, 1));
            mt1 = fmaxf(mt1, __shfl_xor_sync(0xffffffffu, mt1, 2));
            const float mn0 = fmaxf(m0, mt0), mn1 = fmaxf(m1, mt1);
            const float corr0 = __expf(m0 - mn0), corr1 = __expf(m1 - mn1);
            m0 = mn0; m1 = mn1;
            float rs0 = 0.0f, rs1 = 0.0f;
#pragma unroll
            for (int j = 0; j < 8; j++) {
                s[j][0] = __expf(s[j][0] - mn0);
                s[j][1] = __expf(s[j][1] - mn0);
                s[j][2] = __expf(s[j][2] - mn1);
                s[j][3] = __expf(s[j][3] - mn1);
                rs0 += s[j][0] + s[j][1];
                rs1 += s[j][2] + s[j][3];
            }
            rs0 += __shfl_xor_sync(0xffffffffu, rs0, 1);
            rs0 += __shfl_xor_sync(0xffffffffu, rs0, 2);
            rs1 += __shfl_xor_sync(0xffffffffu, rs1, 1);
            rs1 += __shfl_xor_sync(0xffffffffu, rs1, 2);
            l0 = l0 * corr0 + rs0;
            l1 = l1 * corr1 + rs1;
#pragma unroll
            for (int n = 0; n < 16; n++) {
                O[n][0] *= corr0;  O[n][1] *= corr0;
                O[n][2] *= corr1;  O[n][3] *= corr1;
            }

#pragma unroll
            for (int kt = 0; kt < 4; kt++) {
                uint32_t ph[4], pl[4];
                ph[0] = packbf2(s[2 * kt][0], s[2 * kt][1]);
                pl[0] = packbf2(s[2 * kt][0] - bf_low(ph[0]), s[2 * kt][1] - bf_high(ph[0]));
                ph[1] = packbf2(s[2 * kt][2], s[2 * kt][3]);
                pl[1] = packbf2(s[2 * kt][2] - bf_low(ph[1]), s[2 * kt][3] - bf_high(ph[1]));
                ph[2] = packbf2(s[2 * kt + 1][0], s[2 * kt + 1][1]);
                pl[2] = packbf2(s[2 * kt + 1][0] - bf_low(ph[2]), s[2 * kt + 1][1] - bf_high(ph[2]));
                ph[3] = packbf2(s[2 * kt + 1][2], s[2 * kt + 1][3]);
                pl[3] = packbf2(s[2 * kt + 1][2] - bf_low(ph[3]), s[2 * kt + 1][3] - bf_high(ph[3]));
#pragma unroll
                for (int g = 0; g < 8; g++) {
                    uint32_t vb[4];
                    uint32_t base = Vb + ((kt * 16 + vrow_off) * AQS + g * 16 + vcol8) * 2;
                    ldm_x4_t(vb, base);
                    mma16816(O[2 * g],     ph, vb[0], vb[1]);
                    mma16816(O[2 * g + 1], ph, vb[2], vb[3]);
                    mma16816(O[2 * g],     pl, vb[0], vb[1]);
                    mma16816(O[2 * g + 1], pl, vb[2], vb[3]);
                    ldm_x4_t(vb, base + 256);
                    mma16816(O[2 * g],     ph, vb[0], vb[1]);
                    mma16816(O[2 * g + 1], ph, vb[2], vb[3]);
                }
            }
        }
        __syncthreads();
    }

    // ---- normalize + split-store to g_asplit [hi|lo] fp16 ----
    const float inv0 = 1.0f / l0, inv1 = 1.0f / l1;
    const int sr0 = wrow + (lane >> 2), sr1 = sr0 + 8;
#pragma unroll
    for (int n = 0; n < 16; n++) {
        const int d = n * 8 + ((lane & 3) << 1);
        {
            float v0 = O[n][0] * inv0, v1 = O[n][1] * inv0;
            __half2 hi = __floats2half2_rn(v0, v1);
            __half2 lo = __floats2half2_rn(v0 - __low2float(hi), v1 - __high2float(hi));
            __half* p = g_asplit + (size_t)sr0 * GK + h * 128 + d;
            *reinterpret_cast<__half2*>(p)       = hi;
            *reinterpret_cast<__half2*>(p + DIM) = lo;
        }
        {
            float v2 = O[n][2] * inv1, v3 = O[n][3] * inv1;
            __half2 hi = __floats2half2_rn(v2, v3);
            __half2 lo = __floats2half2_rn(v2 - __low2float(hi), v3 - __high2float(hi));
            __half* p = g_asplit + (size_t)sr1 * GK + h * 128 + d;
            *reinterpret_cast<__half2*>(p)       = hi;
            *reinterpret_cast<__half2*>(p + DIM) = lo;
        }
    }
}

// ---------------- launch -----------------------------------------------------
// inputs: 0:x 1:start_pos 2:freqs 3:mask 4:wq 5:wk 6:wv 7:wo  (mask analytic)
extern "C" void kernel_launch(void* const* d_in, const int* in_sizes, int n_in,
                              void* d_out, int out_size)
{
    const float* x     = (const float*)d_in[0];
    const float* freqs = (const float*)d_in[2];
    const float* wq    = (const float*)d_in[4];
    const float* wk    = (const float*)d_in[5];
    const float* wv    = (const float*)d_in[6];
    const float* wo    = (const float*)d_in[7];
    float* out = (float*)d_out;

    cudaFuncSetAttribute(attn_kernel, cudaFuncAttributeMaxDynamicSharedMemorySize, ATTN_SMEM);

    convert_w_kernel<<<dim3(DIM * DIM / 4 / 256, 1, 4), 256>>>(wq, wk, wv, wo);
    convert_x_kernel<<<SEQ * DIM / 4 / 256, 256>>>(x);
    qkv_gemm_kernel<<<dim3(SEQ / 128, DIM / 128, 3), 256>>>(freqs);
    attn_kernel<<<dim3(SEQ / 128, NH), 256, ATTN_SMEM>>>();
    out_gemm_kernel<<<dim3(SEQ / 128, DIM / 128, 1), 256>>>(out);
}

// round 9
// speedup vs baseline: 2.5966x; 1.0261x over previous
#include <cuda_runtime.h>
#include <cuda_fp16.h>
#include <math.h>
#include <stdint.h>

#define SEQ 2048
#define DIM 4096
#define NH  32
#define HD  128
#define GK  8192    // A-side 2-segment fp16 K-concat: A=[hi|lo]; B = W_hi read twice

// ---------------- scratch (__device__ globals; no cudaMalloc allowed) -------
__device__ __half g_wh[4ull * DIM * DIM];                // weights hi, single copy
__device__ __half g_xsplit[(size_t)SEQ * GK];            // x        [hi|lo]
__device__ __half g_asplit[(size_t)SEQ * GK];            // attn out [hi|lo]
__device__ __half g_qs[(size_t)SEQ * NH * 256];          // q per head [hi128|lo128]
__device__ __half g_ks[(size_t)SEQ * NH * 128];          // k per head, plain fp16
__device__ __half g_vs[(size_t)SEQ * NH * 128];          // v per head, plain fp16

// ---------------- PTX helpers ----------------------------------------------
__device__ __forceinline__ uint32_t smem_u32(const void* p) {
    uint32_t a;
    asm("{ .reg .u64 t; cvta.to.shared.u64 t, %1; cvt.u32.u64 %0, t; }" : "=r"(a) : "l"(p));
    return a;
}
__device__ __forceinline__ void cp_async16(uint32_t dst, const void* src) {
    asm volatile("cp.async.cg.shared.global [%0], [%1], 16;" :: "r"(dst), "l"(src));
}
#define CP_COMMIT()  asm volatile("cp.async.commit_group;" ::: "memory")
#define CP_WAIT(n)   asm volatile("cp.async.wait_group %0;" :: "n"(n) : "memory")

__device__ __forceinline__ void ldm_x4(uint32_t* r, uint32_t addr) {
    asm volatile("ldmatrix.sync.aligned.m8n8.x4.shared.b16 {%0,%1,%2,%3}, [%4];"
        : "=r"(r[0]), "=r"(r[1]), "=r"(r[2]), "=r"(r[3]) : "r"(addr));
}
__device__ __forceinline__ void ldm_x4_t(uint32_t* r, uint32_t addr) {
    asm volatile("ldmatrix.sync.aligned.m8n8.x4.trans.shared.b16 {%0,%1,%2,%3}, [%4];"
        : "=r"(r[0]), "=r"(r[1]), "=r"(r[2]), "=r"(r[3]) : "r"(addr));
}
// fp16 mma, fp32 accum
__device__ __forceinline__ void mma16816h(float* c, const uint32_t* a, uint32_t b0, uint32_t b1) {
    asm volatile(
        "mma.sync.aligned.m16n8k16.row.col.f32.f16.f16.f32 "
        "{%0,%1,%2,%3}, {%4,%5,%6,%7}, {%8,%9}, {%0,%1,%2,%3};"
        : "+f"(c[0]), "+f"(c[1]), "+f"(c[2]), "+f"(c[3])
        : "r"(a[0]), "r"(a[1]), "r"(a[2]), "r"(a[3]), "r"(b0), "r"(b1));
}
__device__ __forceinline__ uint32_t packh2(float lo, float hi) {
    __half2 h = __floats2half2_rn(lo, hi);
    return *reinterpret_cast<uint32_t*>(&h);
}
__device__ __forceinline__ float h2_low(uint32_t r)  { return __low2float(*reinterpret_cast<__half2*>(&r)); }
__device__ __forceinline__ float h2_high(uint32_t r) { return __high2float(*reinterpret_cast<__half2*>(&r)); }

// ---------------- fp32 -> fp16 hi/lo split converters -----------------------
__device__ __forceinline__ void split4h(const float4 v, __half* hi, __half* lo) {
    float f[4] = {v.x, v.y, v.z, v.w};
#pragma unroll
    for (int i = 0; i < 4; i++) {
        hi[i] = __float2half_rn(f[i]);
        lo[i] = __float2half_rn(f[i] - __half2float(hi[i]));
    }
}

// Weights: single hi copy [DIM x DIM]
__global__ __launch_bounds__(256) void convert_w_kernel(
    const float* __restrict__ w0, const float* __restrict__ w1,
    const float* __restrict__ w2, const float* __restrict__ w3)
{
    const float* w = (blockIdx.z == 0) ? w0 : (blockIdx.z == 1) ? w1 :
                     (blockIdx.z == 2) ? w2 : w3;
    __half* dst = g_wh + (size_t)blockIdx.z * DIM * DIM;
    int idx = blockIdx.x * 256 + threadIdx.x;
    float4 v = reinterpret_cast<const float4*>(w)[idx];
    __half hi[4];
    hi[0] = __float2half_rn(v.x); hi[1] = __float2half_rn(v.y);
    hi[2] = __float2half_rn(v.z); hi[3] = __float2half_rn(v.w);
    *reinterpret_cast<uint2*>(dst + (size_t)idx * 4) = *reinterpret_cast<uint2*>(hi);
}

// x: [hi | lo]
__global__ __launch_bounds__(256) void convert_x_kernel(const float* __restrict__ x)
{
    int idx = blockIdx.x * 256 + threadIdx.x;
    int row = idx >> 10;
    int c4  = (idx & 1023) << 2;
    __half hi[4], lo[4];
    split4h(reinterpret_cast<const float4*>(x)[idx], hi, lo);
    size_t base = (size_t)row * GK + c4;
    *reinterpret_cast<uint2*>(g_xsplit + base)       = *reinterpret_cast<uint2*>(hi);
    *reinterpret_cast<uint2*>(g_xsplit + base + DIM) = *reinterpret_cast<uint2*>(lo);
}

// ---------------- HMMA fp16 GEMM, 3-stage single-sync pipeline --------------
// C[128x128] = A'[M,GK] . B'[N,GK]^T (B col k reads W_hi col k&4095).
// 256 threads, 8 warps (4m x 2n), warp tile 32x64, BK=32.
#define BK 32
#define NKSTEP (GK / BK)     // 256
#define ASTR 40
#define GSTAGES 3
#define GEMM_SMEM (GSTAGES * 2 * 128 * ASTR * (int)sizeof(__half))  // 61440

__device__ __forceinline__ void hgemm_body(
    const __half* __restrict__ A,
    const __half* __restrict__ B,          // [4096 x 4096] hi
    float* __restrict__ C,                 // omode 0
    __half* __restrict__ hdst,             // omode 1 (q split) / 2 (plain kv)
    int omode,
    const float* __restrict__ freqs, int rope, float qsc,
    int m0, int n0)
{
    extern __shared__ __half gsm[];
    __half* sA = gsm;                          // GSTAGES x 128 x ASTR
    __half* sB = gsm + GSTAGES * 128 * ASTR;   // GSTAGES x 128 x ASTR

    const int tid  = threadIdx.x;
    const int wid  = tid >> 5;
    const int lane = tid & 31;
    const int wm   = wid >> 1;   // 0..3 -> rows wm*32
    const int wn   = wid & 1;    // 0..1 -> cols wn*64

    float acc[2][8][4];
#pragma unroll
    for (int mi = 0; mi < 2; mi++)
#pragma unroll
        for (int ni = 0; ni < 8; ni++)
#pragma unroll
            for (int j = 0; j < 4; j++) acc[mi][ni][j] = 0.0f;

    const __half* agp = A + (size_t)m0 * GK;
    const __half* bgp = B + (size_t)n0 * DIM;

    const int r0c = tid >> 2, seg0 = (tid & 3);
    const int r1c = (tid + 256) >> 2, seg1 = ((tid + 256) & 3);

    auto load_tile = [&](int kstep, int s) {
        const size_t ka = (size_t)kstep * BK;
        const size_t kb = ka & (DIM - 1);          // B: read hi segment twice
        __half* a0 = sA + (s * 128 + r0c) * ASTR + seg0 * 8;
        __half* b0 = sB + (s * 128 + r0c) * ASTR + seg0 * 8;
        __half* a1 = sA + (s * 128 + r1c) * ASTR + seg1 * 8;
        __half* b1 = sB + (s * 128 + r1c) * ASTR + seg1 * 8;
        cp_async16(smem_u32(a0), agp + (size_t)r0c * GK  + ka + seg0 * 8);
        cp_async16(smem_u32(b0), bgp + (size_t)r0c * DIM + kb + seg0 * 8);
        cp_async16(smem_u32(a1), agp + (size_t)r1c * GK  + ka + seg1 * 8);
        cp_async16(smem_u32(b1), bgp + (size_t)r1c * DIM + kb + seg1 * 8);
        CP_COMMIT();
    };

    load_tile(0, 0);
    load_tile(1, 1);

    for (int k = 0; k < NKSTEP; k++) {
        if (k + 1 < NKSTEP) { CP_WAIT(1); } else { CP_WAIT(0); }
        __syncthreads();                 // stage k visible to all; frees stage (k-1)%3
        if (k + 2 < NKSTEP) load_tile(k + 2, (k + 2) % GSTAGES);

        const int s = k % GSTAGES;
#pragma unroll
        for (int kk = 0; kk < 2; kk++) {
            const int k0 = kk * 16;
            uint32_t af[2][4], bf[8][2];
#pragma unroll
            for (int mi = 0; mi < 2; mi++) {
                int row = wm * 32 + mi * 16 + (lane & 15);
                ldm_x4(af[mi], smem_u32(sA + (s * 128 + row) * ASTR + k0 + ((lane >> 4) << 3)));
            }
#pragma unroll
            for (int np = 0; np < 4; np++) {
                int rown = wn * 64 + np * 16 + ((lane >> 4) << 3) + (lane & 7);
                uint32_t b[4];
                ldm_x4(b, smem_u32(sB + (s * 128 + rown) * ASTR + k0 + (((lane >> 3) & 1) << 3)));
                bf[2 * np][0] = b[0];  bf[2 * np][1] = b[1];
                bf[2 * np + 1][0] = b[2];  bf[2 * np + 1][1] = b[3];
            }
#pragma unroll
            for (int mi = 0; mi < 2; mi++)
#pragma unroll
                for (int ni = 0; ni < 8; ni++)
                    mma16816h(acc[mi][ni], af[mi], bf[ni][0], bf[ni][1]);
        }
    }

#pragma unroll
    for (int mi = 0; mi < 2; mi++) {
        const int ra = m0 + wm * 32 + mi * 16 + (lane >> 2);
        const int rb = ra + 8;
#pragma unroll
        for (int ni = 0; ni < 8; ni++) {
            const int col = n0 + wn * 64 + ni * 8 + ((lane & 3) << 1);
            float d0 = acc[mi][ni][0], d1 = acc[mi][ni][1];
            float d2 = acc[mi][ni][2], d3 = acc[mi][ni][3];
            if (rope) {
                const int hd = col & (HD - 1);          // even
                float ca = freqs[ra * HD + hd], sa = freqs[ra * HD + hd + 1];
                float cb = freqs[rb * HD + hd], sb = freqs[rb * HD + hd + 1];
                d0 *= (ca - sa) * qsc;  d1 *= (ca + sa) * qsc;
                d2 *= (cb - sb) * qsc;  d3 *= (cb + sb) * qsc;
            }
            if (omode == 1) {                       // q: split [hi|lo]
                const int head = col >> 7, d = col & 127;
                __half* pa = hdst + ((size_t)ra * NH + head) * 256 + d;
                uint32_t hi = packh2(d0, d1);
                uint32_t lo = packh2(d0 - h2_low(hi), d1 - h2_high(hi));
                *reinterpret_cast<uint32_t*>(pa)       = hi;
                *reinterpret_cast<uint32_t*>(pa + 128) = lo;
                __half* pb = hdst + ((size_t)rb * NH + head) * 256 + d;
                hi = packh2(d2, d3);
                lo = packh2(d2 - h2_low(hi), d3 - h2_high(hi));
                *reinterpret_cast<uint32_t*>(pb)       = hi;
                *reinterpret_cast<uint32_t*>(pb + 128) = lo;
            } else if (omode == 2) {                // k/v: plain fp16
                const int head = col >> 7, d = col & 127;
                *reinterpret_cast<uint32_t*>(hdst + ((size_t)ra * NH + head) * 128 + d) = packh2(d0, d1);
                *reinterpret_cast<uint32_t*>(hdst + ((size_t)rb * NH + head) * 128 + d) = packh2(d2, d3);
            } else {
                *reinterpret_cast<float2*>(&C[(size_t)ra * DIM + col]) = make_float2(d0, d1);
                *reinterpret_cast<float2*>(&C[(size_t)rb * DIM + col]) = make_float2(d2, d3);
            }
        }
    }
}

__global__ __launch_bounds__(256, 2) void qkv_gemm_kernel(const float* __restrict__ freqs)
{
    const int z = blockIdx.z;
    const __half* B = g_wh + (size_t)z * DIM * DIM;
    __half* dst = (z == 0) ? g_qs : (z == 1) ? g_ks : g_vs;
    const float qsc = (z == 0) ? 0.08838834764831845f : 1.0f;
    hgemm_body(g_xsplit, B, nullptr, dst, (z == 0) ? 1 : 2, freqs, (z < 2) ? 1 : 0, qsc,
               blockIdx.x * 128, blockIdx.y * 128);
}

__global__ __launch_bounds__(256, 2) void out_gemm_kernel(float* __restrict__ out)
{
    hgemm_body(g_asplit, g_wh + 3ull * DIM * DIM, out, nullptr, 0, nullptr, 0, 1.0f,
               blockIdx.x * 128, blockIdx.y * 128);
}

// ---------------- fp16 flash attention (2-segment) --------------------------
// CTA: 128 q x 64 kv, 8 warps. q split [hi|lo]; K,V plain fp16.
// S = q_hi.K + q_lo.K ; O += P_hi.V + P_lo.V
#define AQS 264                       // q smem row stride (256 + 8)
#define KVS 136                       // k/v smem row stride (128 + 8)
#define ATTN_SMEM ((128 * AQS + 4 * 64 * KVS) * (int)sizeof(__half))

__global__ __launch_bounds__(256, 1) void attn_kernel()
{
    extern __shared__ __half sm_attn[];
    __half* sQ = sm_attn;                  // 128 x AQS
    __half* sK = sQ + 128 * AQS;           // 2 x 64 x KVS
    __half* sV = sK + 2 * 64 * KVS;        // 2 x 64 x KVS

    const int h   = blockIdx.y;
    const int q0  = blockIdx.x * 128;
    const int tid = threadIdx.x;
    const int wid = tid >> 5, lane = tid & 31;

    for (int i = tid; i < 128 * 32; i += 256) {
        int r = i >> 5, c = i & 31;
        cp_async16(smem_u32(sQ + r * AQS) + c * 16,
                   g_qs + ((size_t)(q0 + r) * NH + h) * 256 + c * 8);
    }
    CP_COMMIT();

    const int nt = q0 / 64 + 2;

    auto load_kv = [&](int t, int s) {
        for (int i = tid; i < 64 * 16 * 2; i += 256) {
            int half_sel = i >= 64 * 16;
            int j = i & (64 * 16 - 1);
            int r = j >> 4, c = j & 15;
            size_t src = ((size_t)(t * 64 + r) * NH + h) * 128 + c * 8;
            __half* dst = (half_sel ? sV : sK) + (s * 64 + r) * KVS + c * 8;
            cp_async16(smem_u32(dst), (half_sel ? g_vs : g_ks) + src);
        }
        CP_COMMIT();
    };
    load_kv(0, 0);

    float m0 = -1e30f, m1 = -1e30f, l0 = 0.0f, l1 = 0.0f;
    float O[16][4];
#pragma unroll
    for (int n = 0; n < 16; n++)
#pragma unroll
        for (int j = 0; j < 4; j++) O[n][j] = 0.0f;

    const int wrow = q0 + wid * 16;
    const int r0g  = wrow + (lane >> 2);
    const uint32_t Qb = smem_u32(sQ);
    const uint32_t qrow_off = (uint32_t)((wid * 16 + (lane & 15)) * AQS + ((lane >> 4) << 3));
    const uint32_t krow = (uint32_t)(((lane >> 4) << 3) + (lane & 7));
    const uint32_t kcol = (uint32_t)(((lane >> 3) & 1) << 3);
    const uint32_t vrow_off = (uint32_t)(lane & 15);
    const uint32_t vcol8 = (uint32_t)((lane >> 4) << 3);

    for (int t = 0; t < nt; t++) {
        if (t + 1 < nt) { load_kv(t + 1, (t + 1) & 1); CP_WAIT(1); }
        else           { CP_WAIT(0); }
        __syncthreads();
        const int k0 = t * 64;

        if (k0 <= wrow + 15) {
            const uint32_t Kb = smem_u32(sK + (t & 1) * 64 * KVS);
            const uint32_t Vb = smem_u32(sV + (t & 1) * 64 * KVS);

            float s[8][4];
#pragma unroll
            for (int j = 0; j < 8; j++)
#pragma unroll
                for (int i = 0; i < 4; i++) s[j][i] = 0.0f;

            // ---- S = (q_hi + q_lo) . K ----
#pragma unroll
            for (int kk = 0; kk < 8; kk++) {
                uint32_t qh[4], ql[4];
                ldm_x4(qh, Qb + (qrow_off + kk * 16) * 2);
                ldm_x4(ql, Qb + (qrow_off + 128 + kk * 16) * 2);
#pragma unroll
                for (int g = 0; g < 4; g++) {
                    uint32_t kb[4];
                    ldm_x4(kb, Kb + ((g * 16 + krow) * KVS + kcol + kk * 16) * 2);
                    mma16816h(s[2 * g],     qh, kb[0], kb[1]);
                    mma16816h(s[2 * g + 1], qh, kb[2], kb[3]);
                    mma16816h(s[2 * g],     ql, kb[0], kb[1]);
                    mma16816h(s[2 * g + 1], ql, kb[2], kb[3]);
                }
            }

            if (k0 + 63 > wrow) {
                const int c0 = k0 + ((lane & 3) << 1);
#pragma unroll
                for (int j = 0; j < 8; j++) {
                    int cc = c0 + j * 8;
                    if (cc     > r0g)     s[j][0] = -1e30f;
                    if (cc + 1 > r0g)     s[j][1] = -1e30f;
                    if (cc     > r0g + 8) s[j][2] = -1e30f;
                    if (cc + 1 > r0g + 8) s[j][3] = -1e30f;
                }
            }

            float mt0 = -1e30f, mt1 = -1e30f;
#pragma unroll
            for (int j = 0; j < 8; j++) {
                mt0 = fmaxf(mt0, fmaxf(s[j][0], s[j][1]));
                mt1 = fmaxf(mt1, fmaxf(s[j][2], s[j][3]));
            }
            mt0 = fmaxf(mt0, __shfl_xor_sync(0xffffffffu, mt0, 1));
            mt0 = fmaxf(mt0, __shfl_xor_sync(0xffffffffu, mt0, 2));
            mt1 = fmaxf(mt1, __shfl_xor_sync(0xffffffffu, mt1, 1));
            mt1 = fmaxf(mt1, __shfl_xor_sync(0xffffffffu, mt1, 2));
            const float mn0 = fmaxf(m0, mt0), mn1 = fmaxf(m1, mt1);
            const float corr0 = __expf(m0 - mn0), corr1 = __expf(m1 - mn1);
            m0 = mn0; m1 = mn1;
            float rs0 = 0.0f, rs1 = 0.0f;
#pragma unroll
            for (int j = 0; j < 8; j++) {
                s[j][0] = __expf(s[j][0] - mn0);
                s[j][1] = __expf(s[j][1] - mn0);
                s[j][2] = __expf(s[j][2] - mn1);
                s[j][3] = __expf(s[j][3] - mn1);
                rs0 += s[j][0] + s[j][1];
                rs1 += s[j][2] + s[j][3];
            }
            rs0 += __shfl_xor_sync(0xffffffffu, rs0, 1);
            rs0 += __shfl_xor_sync(0xffffffffu, rs0, 2);
            rs1 += __shfl_xor_sync(0xffffffffu, rs1, 1);
            rs1 += __shfl_xor_sync(0xffffffffu, rs1, 2);
            l0 = l0 * corr0 + rs0;
            l1 = l1 * corr1 + rs1;
#pragma unroll
            for (int n = 0; n < 16; n++) {
                O[n][0] *= corr0;  O[n][1] *= corr0;
                O[n][2] *= corr1;  O[n][3] *= corr1;
            }

            // ---- O += (P_hi + P_lo) . V ----
#pragma unroll
            for (int kt = 0; kt < 4; kt++) {
                uint32_t ph[4], pl[4];
                ph[0] = packh2(s[2 * kt][0], s[2 * kt][1]);
                pl[0] = packh2(s[2 * kt][0] - h2_low(ph[0]), s[2 * kt][1] - h2_high(ph[0]));
                ph[1] = packh2(s[2 * kt][2], s[2 * kt][3]);
                pl[1] = packh2(s[2 * kt][2] - h2_low(ph[1]), s[2 * kt][3] - h2_high(ph[1]));
                ph[2] = packh2(s[2 * kt + 1][0], s[2 * kt + 1][1]);
                pl[2] = packh2(s[2 * kt + 1][0] - h2_low(ph[2]), s[2 * kt + 1][1] - h2_high(ph[2]));
                ph[3] = packh2(s[2 * kt + 1][2], s[2 * kt + 1][3]);
                pl[3] = packh2(s[2 * kt + 1][2] - h2_low(ph[3]), s[2 * kt + 1][3] - h2_high(ph[3]));
#pragma unroll
                for (int g = 0; g < 8; g++) {
                    uint32_t vb[4];
                    ldm_x4_t(vb, Vb + ((kt * 16 + vrow_off) * KVS + g * 16 + vcol8) * 2);
                    mma16816h(O[2 * g],     ph, vb[0], vb[1]);
                    mma16816h(O[2 * g + 1], ph, vb[2], vb[3]);
                    mma16816h(O[2 * g],     pl, vb[0], vb[1]);
                    mma16816h(O[2 * g + 1], pl, vb[2], vb[3]);
                }
            }
        }
        __syncthreads();
    }

    // ---- normalize + split-store to g_asplit [hi|lo] fp16 ----
    const float inv0 = 1.0f / l0, inv1 = 1.0f / l1;
    const int sr0 = wrow + (lane >> 2), sr1 = sr0 + 8;
#pragma unroll
    for (int n = 0; n < 16; n++) {
        const int d = n * 8 + ((lane & 3) << 1);
        {
            float v0 = O[n][0] * inv0, v1 = O[n][1] * inv0;
            uint32_t hi = packh2(v0, v1);
            uint32_t lo = packh2(v0 - h2_low(hi), v1 - h2_high(hi));
            __half* p = g_asplit + (size_t)sr0 * GK + h * 128 + d;
            *reinterpret_cast<uint32_t*>(p)       = hi;
            *reinterpret_cast<uint32_t*>(p + DIM) = lo;
        }
        {
            float v2 = O[n][2] * inv1, v3 = O[n][3] * inv1;
            uint32_t hi = packh2(v2, v3);
            uint32_t lo = packh2(v2 - h2_low(hi), v3 - h2_high(hi));
            __half* p = g_asplit + (size_t)sr1 * GK + h * 128 + d;
            *reinterpret_cast<uint32_t*>(p)       = hi;
            *reinterpret_cast<uint32_t*>(p + DIM) = lo;
        }
    }
}

// ---------------- launch -----------------------------------------------------
// inputs: 0:x 1:start_pos 2:freqs 3:mask 4:wq 5:wk 6:wv 7:wo  (mask analytic)
extern "C" void kernel_launch(void* const* d_in, const int* in_sizes, int n_in,
                              void* d_out, int out_size)
{
    const float* x     = (const float*)d_in[0];
    const float* freqs = (const float*)d_in[2];
    const float* wq    = (const float*)d_in[4];
    const float* wk    = (const float*)d_in[5];
    const float* wv    = (const float*)d_in[6];
    const float* wo    = (const float*)d_in[7];
    float* out = (float*)d_out;

    cudaFuncSetAttribute(attn_kernel,     cudaFuncAttributeMaxDynamicSharedMemorySize, ATTN_SMEM);
    cudaFuncSetAttribute(qkv_gemm_kernel, cudaFuncAttributeMaxDynamicSharedMemorySize, GEMM_SMEM);
    cudaFuncSetAttribute(out_gemm_kernel, cudaFuncAttributeMaxDynamicSharedMemorySize, GEMM_SMEM);

    convert_w_kernel<<<dim3(DIM * DIM / 4 / 256, 1, 4), 256>>>(wq, wk, wv, wo);
    convert_x_kernel<<<SEQ * DIM / 4 / 256, 256>>>(x);
    qkv_gemm_kernel<<<dim3(SEQ / 128, DIM / 128, 3), 256, GEMM_SMEM>>>(freqs);
    attn_kernel<<<dim3(SEQ / 128, NH), 256, ATTN_SMEM>>>();
    out_gemm_kernel<<<dim3(SEQ / 128, DIM / 128, 1), 256, GEMM_SMEM>>>(out);
}